// round 4
// baseline (speedup 1.0000x reference)
#include <cuda_runtime.h>
#include <cstddef>

#define Bsz  1024
#define Tsz  128
#define Isz  128
#define Hsz  256
#define Ksz  8
#define E1sz 512
#define E2sz 256

typedef unsigned long long u64;

// ---------------------------------------------------------------------------
// f32x2 packed-FMA helpers (sm_100+): doubles fp32 FMA throughput
// ---------------------------------------------------------------------------
__device__ __forceinline__ u64 ffma2(u64 a, u64 b, u64 c){
    u64 d; asm("fma.rn.f32x2 %0, %1, %2, %3;" : "=l"(d) : "l"(a), "l"(b), "l"(c)); return d;
}
__device__ __forceinline__ void unpack2(u64 v, float& lo, float& hi){
    asm("mov.b64 {%0, %1}, %2;" : "=f"(lo), "=f"(hi) : "l"(v));
}
__device__ __forceinline__ float sigmoidf_(float x){
    return __fdividef(1.0f, 1.0f + __expf(-x));
}
__device__ __forceinline__ float tanhf_(float x){
    // accurate enough (~1e-7 rel) via MUFU ex2 + rcp; saturates correctly at +-inf
    return 1.0f - __fdividef(2.0f, __expf(2.0f * x) + 1.0f);
}

// ---------------------------------------------------------------------------
// Scratch (static __device__ arrays: no allocation inside kernel_launch)
// ---------------------------------------------------------------------------
__device__ float g_hl0[(size_t)Tsz * Bsz * Hsz];     // layer-0 outputs, all T (134 MB)
__device__ float g_h1buf[2][(size_t)Bsz * Hsz];      // layer-1 ping-pong
__device__ float g_q[Bsz * Ksz];
__device__ float g_e1[(size_t)Ksz * Bsz * E1sz];     // expert hidden 1
__device__ float g_e2[(size_t)Ksz * Bsz * E2sz];     // expert hidden 2

// ---------------------------------------------------------------------------
// Fused GRU step: one time step. CTA tile = 64 batch rows x 32 hidden cols,
// computes all 3 gates (r,z,n) for its tile, applies gate math in epilogue.
//   gi = x_t @ W_ih^T   (phase 1, K = KIN)
//   gh = h   @ W_hh^T   (phase 2, K = H; skipped when FIRST since h = 0)
//   r = sig(gi_r + bih_r + gh_r + bhh_r); z likewise
//   n = tanh(gi_n + bih_n + r*(gh_n + bhh_n)); h' = (1-z)n + z h
// Grid: (16, 8) = 128 CTAs, 256 threads.
// ---------------------------------------------------------------------------
template<int KIN, bool FIRST>
__global__ void __launch_bounds__(256) gru_step_kernel(
    const float* __restrict__ X, long xstride,
    const float* __restrict__ Wih, const float* __restrict__ Whh,
    const float* __restrict__ bih, const float* __restrict__ bhh,
    const float* __restrict__ Hprev, float* __restrict__ Hnew)
{
    __shared__ float2 As[32][64];      // A value duplicated: As[k][m] = {a,a}
    __shared__ float  Ws[3][32][32];   // Ws[gate][k][j], j = hidden col in tile
    __shared__ float  sB[6][32];       // bih_r,bih_z,bih_n,bhh_r,bhh_z,bhh_n

    const int tid = threadIdx.x;
    const int tx  = tid & 15;          // column pair: cols {2tx, 2tx+1}
    const int ty  = tid >> 4;          // rows {4ty .. 4ty+3}
    const int m0  = blockIdx.x * 64;
    const int n0  = blockIdx.y * 32;

    if (tid < 192){
        int g = tid >> 5, j = tid & 31;
        sB[g][j] = (g < 3) ? bih[g * Hsz + n0 + j] : bhh[(g - 3) * Hsz + n0 + j];
    }

    u64 accI[3][4], accH[3][4];
    #pragma unroll
    for (int g = 0; g < 3; g++)
        #pragma unroll
        for (int r = 0; r < 4; r++){ accI[g][r] = 0ull; accH[g][r] = 0ull; }

    // ---------------- phase 1: X @ Wih^T ----------------
    for (int kk = 0; kk < KIN; kk += 32){
        __syncthreads();
        {
            int row = tid >> 2;
            const float* ar = X + (size_t)(m0 + row) * (size_t)xstride + kk;
            #pragma unroll
            for (int hh = 0; hh < 2; hh++){
                int kb = ((tid & 3) << 2) + (hh << 4);
                float4 v = *reinterpret_cast<const float4*>(ar + kb);
                As[kb + 0][row] = make_float2(v.x, v.x);
                As[kb + 1][row] = make_float2(v.y, v.y);
                As[kb + 2][row] = make_float2(v.z, v.z);
                As[kb + 3][row] = make_float2(v.w, v.w);
            }
        }
        #pragma unroll
        for (int i = 0; i < 3; i++){
            int idx = tid + (i << 8);
            int g = idx >> 8, j = (idx >> 3) & 31, kq = idx & 7;
            float4 v = *reinterpret_cast<const float4*>(
                Wih + (size_t)(g * Hsz + n0 + j) * KIN + kk + (kq << 2));
            Ws[g][(kq << 2) + 0][j] = v.x;
            Ws[g][(kq << 2) + 1][j] = v.y;
            Ws[g][(kq << 2) + 2][j] = v.z;
            Ws[g][(kq << 2) + 3][j] = v.w;
        }
        __syncthreads();
        #pragma unroll 8
        for (int k = 0; k < 32; k++){
            u64 b0 = *reinterpret_cast<const u64*>(&Ws[0][k][tx << 1]);
            u64 b1 = *reinterpret_cast<const u64*>(&Ws[1][k][tx << 1]);
            u64 b2 = *reinterpret_cast<const u64*>(&Ws[2][k][tx << 1]);
            #pragma unroll
            for (int r = 0; r < 4; r++){
                u64 a = *reinterpret_cast<const u64*>(&As[k][(ty << 2) + r]);
                accI[0][r] = ffma2(a, b0, accI[0][r]);
                accI[1][r] = ffma2(a, b1, accI[1][r]);
                accI[2][r] = ffma2(a, b2, accI[2][r]);
            }
        }
    }

    // ---------------- phase 2: Hprev @ Whh^T ----------------
    if constexpr (!FIRST){
        for (int kk = 0; kk < Hsz; kk += 32){
            __syncthreads();
            {
                int row = tid >> 2;
                const float* ar = Hprev + (size_t)(m0 + row) * Hsz + kk;
                #pragma unroll
                for (int hh = 0; hh < 2; hh++){
                    int kb = ((tid & 3) << 2) + (hh << 4);
                    float4 v = *reinterpret_cast<const float4*>(ar + kb);
                    As[kb + 0][row] = make_float2(v.x, v.x);
                    As[kb + 1][row] = make_float2(v.y, v.y);
                    As[kb + 2][row] = make_float2(v.z, v.z);
                    As[kb + 3][row] = make_float2(v.w, v.w);
                }
            }
            #pragma unroll
            for (int i = 0; i < 3; i++){
                int idx = tid + (i << 8);
                int g = idx >> 8, j = (idx >> 3) & 31, kq = idx & 7;
                float4 v = *reinterpret_cast<const float4*>(
                    Whh + (size_t)(g * Hsz + n0 + j) * Hsz + kk + (kq << 2));
                Ws[g][(kq << 2) + 0][j] = v.x;
                Ws[g][(kq << 2) + 1][j] = v.y;
                Ws[g][(kq << 2) + 2][j] = v.z;
                Ws[g][(kq << 2) + 3][j] = v.w;
            }
            __syncthreads();
            #pragma unroll 8
            for (int k = 0; k < 32; k++){
                u64 b0 = *reinterpret_cast<const u64*>(&Ws[0][k][tx << 1]);
                u64 b1 = *reinterpret_cast<const u64*>(&Ws[1][k][tx << 1]);
                u64 b2 = *reinterpret_cast<const u64*>(&Ws[2][k][tx << 1]);
                #pragma unroll
                for (int r = 0; r < 4; r++){
                    u64 a = *reinterpret_cast<const u64*>(&As[k][(ty << 2) + r]);
                    accH[0][r] = ffma2(a, b0, accH[0][r]);
                    accH[1][r] = ffma2(a, b1, accH[1][r]);
                    accH[2][r] = ffma2(a, b2, accH[2][r]);
                }
            }
        }
    }

    // ---------------- epilogue: gate math ----------------
    #pragma unroll
    for (int r = 0; r < 4; r++){
        int row = m0 + (ty << 2) + r;
        float giv[3][2], ghv[3][2];
        #pragma unroll
        for (int g = 0; g < 3; g++){
            unpack2(accI[g][r], giv[g][0], giv[g][1]);
            if constexpr (FIRST){ ghv[g][0] = 0.0f; ghv[g][1] = 0.0f; }
            else                { unpack2(accH[g][r], ghv[g][0], ghv[g][1]); }
        }
        float2 hp = make_float2(0.0f, 0.0f);
        if constexpr (!FIRST)
            hp = *reinterpret_cast<const float2*>(&Hprev[(size_t)row * Hsz + n0 + (tx << 1)]);
        float outv[2];
        #pragma unroll
        for (int c = 0; c < 2; c++){
            int j = (tx << 1) + c;
            float rg = sigmoidf_(giv[0][c] + sB[0][j] + ghv[0][c] + sB[3][j]);
            float zg = sigmoidf_(giv[1][c] + sB[1][j] + ghv[1][c] + sB[4][j]);
            float ng = tanhf_(giv[2][c] + sB[2][j] + rg * (ghv[2][c] + sB[5][j]));
            float hpv = c ? hp.y : hp.x;
            outv[c] = (1.0f - zg) * ng + zg * hpv;
        }
        *reinterpret_cast<float2*>(&Hnew[(size_t)row * Hsz + n0 + (tx << 1)]) =
            make_float2(outv[0], outv[1]);
    }
}

// ---------------------------------------------------------------------------
// Generic per-expert GEMM: C[e] = relu(A[e] @ W[e]^T + bias[e])
// A row-major [M,Kdim], W row-major [Ndim,Kdim]. Tile 64x64, 256 threads.
// ---------------------------------------------------------------------------
__global__ void __launch_bounds__(256) gemm_relu_kernel(
    const float* __restrict__ Abase, size_t aStride,
    const float* __restrict__ Wbase, size_t wStride,
    const float* __restrict__ biasBase, size_t bStride,
    float* __restrict__ Cbase, size_t cStride,
    int Kdim, int Ndim)
{
    const int e = blockIdx.z;
    const float* A    = Abase    + (size_t)e * aStride;
    const float* W    = Wbase    + (size_t)e * wStride;
    const float* bias = biasBase + (size_t)e * bStride;
    float*       C    = Cbase    + (size_t)e * cStride;

    const int m0 = blockIdx.x * 64, n0 = blockIdx.y * 64;
    const int tid = threadIdx.x, tx = tid & 15, ty = tid >> 4;

    __shared__ float2 As[32][64];
    __shared__ float  Ws[32][64];

    u64 acc[4][2];
    #pragma unroll
    for (int r = 0; r < 4; r++){ acc[r][0] = 0ull; acc[r][1] = 0ull; }

    for (int kk = 0; kk < Kdim; kk += 32){
        __syncthreads();
        {
            int row = tid >> 2;
            const float* ar = A + (size_t)(m0 + row) * Kdim + kk;
            const float* wr = W + (size_t)(n0 + row) * Kdim + kk;
            #pragma unroll
            for (int hh = 0; hh < 2; hh++){
                int kb = ((tid & 3) << 2) + (hh << 4);
                float4 va = *reinterpret_cast<const float4*>(ar + kb);
                As[kb + 0][row] = make_float2(va.x, va.x);
                As[kb + 1][row] = make_float2(va.y, va.y);
                As[kb + 2][row] = make_float2(va.z, va.z);
                As[kb + 3][row] = make_float2(va.w, va.w);
                float4 vw = *reinterpret_cast<const float4*>(wr + kb);
                Ws[kb + 0][row] = vw.x;
                Ws[kb + 1][row] = vw.y;
                Ws[kb + 2][row] = vw.z;
                Ws[kb + 3][row] = vw.w;
            }
        }
        __syncthreads();
        #pragma unroll 8
        for (int k = 0; k < 32; k++){
            u64 b0 = *reinterpret_cast<const u64*>(&Ws[k][tx << 1]);
            u64 b1 = *reinterpret_cast<const u64*>(&Ws[k][(tx << 1) + 32]);
            #pragma unroll
            for (int r = 0; r < 4; r++){
                u64 a = *reinterpret_cast<const u64*>(&As[k][(ty << 2) + r]);
                acc[r][0] = ffma2(a, b0, acc[r][0]);
                acc[r][1] = ffma2(a, b1, acc[r][1]);
            }
        }
    }

    #pragma unroll
    for (int r = 0; r < 4; r++){
        int row = m0 + (ty << 2) + r;
        #pragma unroll
        for (int p = 0; p < 2; p++){
            int j = (tx << 1) + (p << 5);
            float c0, c1;
            unpack2(acc[r][p], c0, c1);
            c0 = fmaxf(c0 + bias[n0 + j],     0.0f);
            c1 = fmaxf(c1 + bias[n0 + j + 1], 0.0f);
            *reinterpret_cast<float2*>(&C[(size_t)row * Ndim + n0 + j]) = make_float2(c0, c1);
        }
    }
}

// ---------------------------------------------------------------------------
// Soft cluster assignment q (Student-t, alpha=1). One warp per batch row.
// ---------------------------------------------------------------------------
__global__ void __launch_bounds__(256) qkernel(
    const float* __restrict__ z, const float* __restrict__ cent, float* __restrict__ q)
{
    int warp = threadIdx.x >> 5, lane = threadIdx.x & 31;
    int b = blockIdx.x * 8 + warp;
    float zr[8];
    #pragma unroll
    for (int i = 0; i < 8; i++) zr[i] = z[(size_t)b * Hsz + lane + 32 * i];
    float s = 0.0f;
    for (int k = 0; k < Ksz; k++){
        float d = 0.0f;
        #pragma unroll
        for (int i = 0; i < 8; i++){
            float t = zr[i] - cent[k * Hsz + lane + 32 * i];
            d = fmaf(t, t, d);
        }
        #pragma unroll
        for (int off = 16; off; off >>= 1) d += __shfl_xor_sync(0xffffffffu, d, off);
        if (lane == k) s = 1.0f / (1.0f + d);
    }
    float tot = s;
    #pragma unroll
    for (int off = 16; off; off >>= 1) tot += __shfl_xor_sync(0xffffffffu, tot, off);
    if (lane < Ksz) q[(size_t)b * Ksz + lane] = s / tot;
}

// ---------------------------------------------------------------------------
// logits + q-weighted combine. One warp per batch row.
// preds[b,c] = sum_k q[b,k] * (h2[b,k,:] . eW3[k,c,:] + eb3[k,c])
// ---------------------------------------------------------------------------
__global__ void __launch_bounds__(256) combine_kernel(
    const float* __restrict__ h2, const float* __restrict__ q,
    const float* __restrict__ eW3, const float* __restrict__ eb3,
    float* __restrict__ out)
{
    int warp = threadIdx.x >> 5, lane = threadIdx.x & 31;
    int b = blockIdx.x * 8 + warp;
    float acc[Ksz][2];
    #pragma unroll
    for (int k = 0; k < Ksz; k++){ acc[k][0] = 0.0f; acc[k][1] = 0.0f; }
    for (int f = lane; f < E2sz; f += 32){
        #pragma unroll
        for (int k = 0; k < Ksz; k++){
            float hv = h2[((size_t)k * Bsz + b) * E2sz + f];
            acc[k][0] = fmaf(hv, eW3[(size_t)(k * 2 + 0) * E2sz + f], acc[k][0]);
            acc[k][1] = fmaf(hv, eW3[(size_t)(k * 2 + 1) * E2sz + f], acc[k][1]);
        }
    }
    #pragma unroll
    for (int k = 0; k < Ksz; k++)
        #pragma unroll
        for (int c = 0; c < 2; c++)
            #pragma unroll
            for (int off = 16; off; off >>= 1)
                acc[k][c] += __shfl_xor_sync(0xffffffffu, acc[k][c], off);
    if (lane == 0){
        float p0 = 0.0f, p1 = 0.0f;
        #pragma unroll
        for (int k = 0; k < Ksz; k++){
            float qq = q[(size_t)b * Ksz + k];
            p0 = fmaf(qq, acc[k][0] + eb3[k * 2 + 0], p0);
            p1 = fmaf(qq, acc[k][1] + eb3[k * 2 + 1], p1);
        }
        out[b * 2 + 0] = p0;
        out[b * 2 + 1] = p1;
    }
}

// ---------------------------------------------------------------------------
// kernel_launch: graph of ~260 kernel nodes, all on the capture stream
// ---------------------------------------------------------------------------
extern "C" void kernel_launch(void* const* d_in, const int* in_sizes, int n_in,
                              void* d_out, int out_size)
{
    const float* x    = (const float*)d_in[0];
    const float* Wih0 = (const float*)d_in[1];
    const float* Whh0 = (const float*)d_in[2];
    const float* bih0 = (const float*)d_in[3];
    const float* bhh0 = (const float*)d_in[4];
    const float* Wih1 = (const float*)d_in[5];
    const float* Whh1 = (const float*)d_in[6];
    const float* bih1 = (const float*)d_in[7];
    const float* bhh1 = (const float*)d_in[8];
    const float* cent = (const float*)d_in[9];
    const float* eW1  = (const float*)d_in[10];
    const float* eb1  = (const float*)d_in[11];
    const float* eW2  = (const float*)d_in[12];
    const float* eb2  = (const float*)d_in[13];
    const float* eW3  = (const float*)d_in[14];
    const float* eb3  = (const float*)d_in[15];
    float* out = (float*)d_out;

    float *hl0, *h1, *qb, *e1, *e2;
    cudaGetSymbolAddress((void**)&hl0, g_hl0);
    cudaGetSymbolAddress((void**)&h1,  g_h1buf);
    cudaGetSymbolAddress((void**)&qb,  g_q);
    cudaGetSymbolAddress((void**)&e1,  g_e1);
    cudaGetSymbolAddress((void**)&e2,  g_e2);

    dim3 sg(16, 8);

    // ---- layer 0: h_l0[t] stored for all t (layer-1 inputs) ----
    gru_step_kernel<Isz, true><<<sg, 256>>>(
        x, (long)(Tsz * Isz), Wih0, Whh0, bih0, bhh0, hl0, hl0);
    for (int t = 1; t < Tsz; t++){
        gru_step_kernel<Isz, false><<<sg, 256>>>(
            x + (size_t)t * Isz, (long)(Tsz * Isz), Wih0, Whh0, bih0, bhh0,
            hl0 + (size_t)(t - 1) * Bsz * Hsz, hl0 + (size_t)t * Bsz * Hsz);
    }

    // ---- layer 1: ping-pong buffers; t writes buf[(t+1)&1]; final z = buf[0] ----
    gru_step_kernel<Hsz, true><<<sg, 256>>>(
        hl0, (long)Hsz, Wih1, Whh1, bih1, bhh1, h1, h1 + (size_t)Bsz * Hsz);
    for (int t = 1; t < Tsz; t++){
        gru_step_kernel<Hsz, false><<<sg, 256>>>(
            hl0 + (size_t)t * Bsz * Hsz, (long)Hsz, Wih1, Whh1, bih1, bhh1,
            h1 + (size_t)(t & 1) * Bsz * Hsz, h1 + (size_t)((t + 1) & 1) * Bsz * Hsz);
    }
    const float* z = h1;   // buf[0] after 128 steps

    // ---- soft clustering ----
    qkernel<<<128, 256>>>(z, cent, qb);

    // ---- experts: h1 = relu(z @ eW1^T + eb1); h2 = relu(h1 @ eW2^T + eb2) ----
    gemm_relu_kernel<<<dim3(16, 8, 8), 256>>>(
        z, (size_t)0,
        eW1, (size_t)E1sz * Hsz,
        eb1, (size_t)E1sz,
        e1,  (size_t)Bsz * E1sz,
        Hsz, E1sz);
    gemm_relu_kernel<<<dim3(16, 4, 8), 256>>>(
        e1, (size_t)Bsz * E1sz,
        eW2, (size_t)E2sz * E1sz,
        eb2, (size_t)E2sz,
        e2,  (size_t)Bsz * E2sz,
        E1sz, E2sz);

    // ---- logits + q-weighted combine ----
    combine_kernel<<<128, 256>>>(e2, qb, eW3, eb3, out);

    (void)in_sizes; (void)n_in; (void)out_size;
}

// round 5
// speedup vs baseline: 1.2561x; 1.2561x over previous
#include <cuda_runtime.h>
#include <cstddef>

#define Bsz  1024
#define Tsz  128
#define Isz  128
#define Hsz  256
#define G3   768
#define Ksz  8
#define E1sz 512
#define E2sz 256

typedef unsigned long long u64;
struct alignas(16) U64x2 { u64 lo, hi; };

__device__ __forceinline__ u64 ffma2(u64 a, u64 b, u64 c){
    u64 d; asm("fma.rn.f32x2 %0, %1, %2, %3;" : "=l"(d) : "l"(a), "l"(b), "l"(c)); return d;
}
__device__ __forceinline__ void unpack2(u64 v, float& lo, float& hi){
    asm("mov.b64 {%0, %1}, %2;" : "=f"(lo), "=f"(hi) : "l"(v));
}
__device__ __forceinline__ u64 pack2(float x, float y){
    u64 v; asm("mov.b64 %0, {%1, %2};" : "=l"(v) : "f"(x), "f"(y)); return v;
}
__device__ __forceinline__ float sigmoidf_(float x){
    return __fdividef(1.0f, 1.0f + __expf(-x));
}
__device__ __forceinline__ float tanhf_(float x){
    return 1.0f - __fdividef(2.0f, __expf(2.0f * x) + 1.0f);
}

// ---------------- scratch ----------------
__device__ float g_xT[(size_t)Tsz * Isz * Bsz];      // [t][k][b]
__device__ float g_WihT0[(size_t)Isz * G3];
__device__ float g_WhhT0[(size_t)Hsz * G3];
__device__ float g_WihT1[(size_t)Hsz * G3];
__device__ float g_WhhT1[(size_t)Hsz * G3];
__device__ float g_gi0[(size_t)Tsz * Bsz * G3];      // [t][b][768]
__device__ float g_gi1[(size_t)Tsz * Bsz * G3];      // [t][b][768]
__device__ float g_hl0T[2][(size_t)Hsz * Bsz];       // ping-pong [h][b]
__device__ float g_h1T[2][(size_t)Hsz * Bsz];
__device__ float g_z[(size_t)Bsz * Hsz];
__device__ float g_q[Bsz * Ksz];
__device__ float g_e1[(size_t)Ksz * Bsz * E1sz];
__device__ float g_e2[(size_t)Ksz * Bsz * E2sz];

// ---------------- strided 32x32 transpose: out[c][r] = in[r][c] ----------------
__global__ void __launch_bounds__(256) transpose_s(
    const float* __restrict__ in, size_t inRS, size_t inZ,
    float* __restrict__ out, size_t outRS, size_t outZ)
{
    in  += (size_t)blockIdx.z * inZ;
    out += (size_t)blockIdx.z * outZ;
    __shared__ float t[32][33];
    const int tx = threadIdx.x & 31, ty = threadIdx.x >> 5;
    const int r0 = blockIdx.y * 32, c0 = blockIdx.x * 32;
    #pragma unroll
    for (int i = 0; i < 4; i++)
        t[ty + 8 * i][tx] = in[(size_t)(r0 + ty + 8 * i) * inRS + c0 + tx];
    __syncthreads();
    #pragma unroll
    for (int i = 0; i < 4; i++)
        out[(size_t)(c0 + ty + 8 * i) * outRS + r0 + tx] = t[tx][ty + 8 * i];
}

// ---------------------------------------------------------------------------
// TN GEMM: C[m][n] = sum_k AT(k,m) * WT[k][n]
// AT(k, m) at  AT + (m/mBlk)*aBlkStride + (m%mBlk) + k*aRowStride
// Tile 128x64, 256 threads, 48KB smem (2 CTAs/SM).
// ---------------------------------------------------------------------------
__global__ void __launch_bounds__(256) gemm_tn(
    const float* __restrict__ AT, size_t aRowStride, size_t aBlkStride, int mBlk,
    const float* __restrict__ WT, int N, int K, float* __restrict__ C)
{
    extern __shared__ float sm[];
    float* As = sm;              // [64][128]
    float* Bs = sm + 64 * 128;   // [64][64]
    const int tid = threadIdx.x, w = tid >> 5, lane = tid & 31;
    const int m0 = blockIdx.x * 128, n0 = blockIdx.y * 64;
    const int jl = w * 8;
    const float* Abase = AT + (size_t)(m0 / mBlk) * aBlkStride + (m0 % mBlk);

    u64 acc[4][4];
    #pragma unroll
    for (int r = 0; r < 4; r++)
        #pragma unroll
        for (int q = 0; q < 4; q++) acc[r][q] = 0ull;

    for (int kk = 0; kk < K; kk += 64){
        __syncthreads();
        for (int i = tid; i < 64 * 32; i += 256){
            int k = i >> 5, q = i & 31;
            *reinterpret_cast<float4*>(As + k * 128 + q * 4) =
                *reinterpret_cast<const float4*>(Abase + (size_t)(kk + k) * aRowStride + q * 4);
        }
        for (int i = tid; i < 64 * 16; i += 256){
            int k = i >> 4, q = i & 15;
            *reinterpret_cast<float4*>(Bs + k * 64 + q * 4) =
                *reinterpret_cast<const float4*>(WT + (size_t)(kk + k) * N + n0 + q * 4);
        }
        __syncthreads();
        #pragma unroll 8
        for (int k = 0; k < 64; k++){
            U64x2 ap = *reinterpret_cast<const U64x2*>(As + k * 128 + 4 * lane);
            float f0, f1, f2, f3;
            unpack2(ap.lo, f0, f1); unpack2(ap.hi, f2, f3);
            u64 ad[4] = { pack2(f0, f0), pack2(f1, f1), pack2(f2, f2), pack2(f3, f3) };
            U64x2 b01 = *reinterpret_cast<const U64x2*>(Bs + k * 64 + jl);
            U64x2 b23 = *reinterpret_cast<const U64x2*>(Bs + k * 64 + jl + 4);
            u64 bq[4] = { b01.lo, b01.hi, b23.lo, b23.hi };
            #pragma unroll
            for (int r = 0; r < 4; r++)
                #pragma unroll
                for (int q = 0; q < 4; q++)
                    acc[r][q] = ffma2(ad[r], bq[q], acc[r][q]);
        }
    }

    #pragma unroll
    for (int r = 0; r < 4; r++){
        int row = m0 + 4 * lane + r;
        float o[8];
        #pragma unroll
        for (int q = 0; q < 4; q++) unpack2(acc[r][q], o[2 * q], o[2 * q + 1]);
        *reinterpret_cast<float4*>(C + (size_t)row * N + n0 + jl) =
            make_float4(o[0], o[1], o[2], o[3]);
        *reinterpret_cast<float4*>(C + (size_t)row * N + n0 + jl + 4) =
            make_float4(o[4], o[5], o[6], o[7]);
    }
}

// ---------------------------------------------------------------------------
// GRU gh-only step (gi precomputed). All H arrays transposed [256][1024].
// CTA tile 64 batch x 32 hidden (x3 gates). Grid (16,8), 256 threads.
// FUSE: additionally computes gi1 = Hprev @ Wih1^T for the SAME tile
// (A already in smem) and writes it to gi1out.
// ---------------------------------------------------------------------------
template<bool FIRST, bool FUSE>
__global__ void __launch_bounds__(256) gru_step(
    const float* __restrict__ HprevT, const float* __restrict__ WhhT,
    const float* __restrict__ WihT1, const float* __restrict__ gi,
    const float* __restrict__ bih, const float* __restrict__ bhh,
    float* __restrict__ HnewT, float* __restrict__ gi1out)
{
    extern __shared__ float sm[];
    float* Bhh = sm;                                   // [256][96]
    float* Bih = sm + 256 * 96;                        // [256][96] (FUSE only)
    float* As  = sm + (FUSE ? 2 : 1) * 256 * 96;       // [64][64]
    const int tid = threadIdx.x, w = tid >> 5, lane = tid & 31;
    const int m0 = blockIdx.x * 64, n0 = blockIdx.y * 32;
    const int jl = w * 4, ml = lane * 2;

    u64 aH[3][2][2], aI[3][2][2];
    #pragma unroll
    for (int g = 0; g < 3; g++)
        #pragma unroll
        for (int cp = 0; cp < 2; cp++)
            #pragma unroll
            for (int r = 0; r < 2; r++){ aH[g][cp][r] = 0ull; aI[g][cp][r] = 0ull; }

    if constexpr (!FIRST){
        // one-time weight slice fill: Bs[k][g*32+j] = WT[k][g*256 + n0 + j]
        for (int i = tid; i < 256 * 24; i += 256){
            int k = i / 24, c = i - k * 24, g = c >> 3, q = c & 7;
            *reinterpret_cast<float4*>(Bhh + k * 96 + g * 32 + q * 4) =
                *reinterpret_cast<const float4*>(WhhT + (size_t)k * G3 + g * Hsz + n0 + q * 4);
            if constexpr (FUSE)
                *reinterpret_cast<float4*>(Bih + k * 96 + g * 32 + q * 4) =
                    *reinterpret_cast<const float4*>(WihT1 + (size_t)k * G3 + g * Hsz + n0 + q * 4);
        }
        for (int kk = 0; kk < Hsz; kk += 64){
            __syncthreads();
            for (int i = tid; i < 64 * 16; i += 256){
                int k = i >> 4, q = i & 15;
                *reinterpret_cast<float4*>(As + k * 64 + q * 4) =
                    *reinterpret_cast<const float4*>(HprevT + (size_t)(kk + k) * Bsz + m0 + q * 4);
            }
            __syncthreads();
            #pragma unroll 8
            for (int k = 0; k < 64; k++){
                u64 a01 = *reinterpret_cast<const u64*>(As + k * 64 + ml);
                float a0f, a1f; unpack2(a01, a0f, a1f);
                u64 a0 = pack2(a0f, a0f), a1 = pack2(a1f, a1f);
                const float* bh = Bhh + (size_t)(kk + k) * 96 + jl;
                #pragma unroll
                for (int g = 0; g < 3; g++){
                    U64x2 bb = *reinterpret_cast<const U64x2*>(bh + g * 32);
                    aH[g][0][0] = ffma2(a0, bb.lo, aH[g][0][0]);
                    aH[g][0][1] = ffma2(a1, bb.lo, aH[g][0][1]);
                    aH[g][1][0] = ffma2(a0, bb.hi, aH[g][1][0]);
                    aH[g][1][1] = ffma2(a1, bb.hi, aH[g][1][1]);
                }
                if constexpr (FUSE){
                    const float* bi2 = Bih + (size_t)(kk + k) * 96 + jl;
                    #pragma unroll
                    for (int g = 0; g < 3; g++){
                        U64x2 bb = *reinterpret_cast<const U64x2*>(bi2 + g * 32);
                        aI[g][0][0] = ffma2(a0, bb.lo, aI[g][0][0]);
                        aI[g][0][1] = ffma2(a1, bb.lo, aI[g][0][1]);
                        aI[g][1][0] = ffma2(a0, bb.hi, aI[g][1][0]);
                        aI[g][1][1] = ffma2(a1, bb.hi, aI[g][1][1]);
                    }
                }
            }
        }
    }

    // ---- epilogue ----
    float gh[3][2][4];
    #pragma unroll
    for (int g = 0; g < 3; g++)
        #pragma unroll
        for (int cp = 0; cp < 2; cp++)
            #pragma unroll
            for (int r = 0; r < 2; r++){
                if constexpr (FIRST){ gh[g][r][2*cp] = 0.0f; gh[g][r][2*cp+1] = 0.0f; }
                else unpack2(aH[g][cp][r], gh[g][r][2*cp], gh[g][r][2*cp+1]);
            }

    float bi[3][4], bh_[3][4];
    #pragma unroll
    for (int g = 0; g < 3; g++){
        *reinterpret_cast<float4*>(bi[g]) =
            *reinterpret_cast<const float4*>(bih + g * Hsz + n0 + jl);
        *reinterpret_cast<float4*>(bh_[g]) =
            *reinterpret_cast<const float4*>(bhh + g * Hsz + n0 + jl);
    }

    float hp[2][4];
    #pragma unroll
    for (int r = 0; r < 2; r++)
        #pragma unroll
        for (int c = 0; c < 4; c++) hp[r][c] = 0.0f;
    if constexpr (!FIRST){
        #pragma unroll
        for (int c = 0; c < 4; c++){
            float2 v = *reinterpret_cast<const float2*>(
                HprevT + (size_t)(n0 + jl + c) * Bsz + m0 + ml);
            hp[0][c] = v.x; hp[1][c] = v.y;
        }
    }

    float hn[2][4];
    #pragma unroll
    for (int r = 0; r < 2; r++){
        const float* gr = gi + (size_t)(m0 + ml + r) * G3;
        float gv[3][4];
        #pragma unroll
        for (int g = 0; g < 3; g++)
            *reinterpret_cast<float4*>(gv[g]) =
                *reinterpret_cast<const float4*>(gr + g * Hsz + n0 + jl);
        #pragma unroll
        for (int c = 0; c < 4; c++){
            float rg = sigmoidf_(gv[0][c] + bi[0][c] + gh[0][r][c] + bh_[0][c]);
            float zg = sigmoidf_(gv[1][c] + bi[1][c] + gh[1][r][c] + bh_[1][c]);
            float ng = tanhf_(gv[2][c] + bi[2][c] + rg * (gh[2][r][c] + bh_[2][c]));
            hn[r][c] = (1.0f - zg) * ng + zg * hp[r][c];
        }
    }
    #pragma unroll
    for (int c = 0; c < 4; c++)
        *reinterpret_cast<float2*>(HnewT + (size_t)(n0 + jl + c) * Bsz + m0 + ml) =
            make_float2(hn[0][c], hn[1][c]);

    if constexpr (FUSE){
        #pragma unroll
        for (int r = 0; r < 2; r++){
            float* go = gi1out + (size_t)(m0 + ml + r) * G3;
            #pragma unroll
            for (int g = 0; g < 3; g++){
                float o0, o1, o2, o3;
                unpack2(aI[g][0][r], o0, o1);
                unpack2(aI[g][1][r], o2, o3);
                *reinterpret_cast<float4*>(go + g * Hsz + n0 + jl) =
                    make_float4(o0, o1, o2, o3);
            }
        }
    }
}

// ---------------------------------------------------------------------------
// Per-expert NT GEMM + relu (proven in R2)
// ---------------------------------------------------------------------------
__global__ void __launch_bounds__(256) gemm_relu_kernel(
    const float* __restrict__ Abase, size_t aStride,
    const float* __restrict__ Wbase, size_t wStride,
    const float* __restrict__ biasBase, size_t bStride,
    float* __restrict__ Cbase, size_t cStride,
    int Kdim, int Ndim)
{
    const int e = blockIdx.z;
    const float* A    = Abase    + (size_t)e * aStride;
    const float* W    = Wbase    + (size_t)e * wStride;
    const float* bias = biasBase + (size_t)e * bStride;
    float*       C    = Cbase    + (size_t)e * cStride;

    const int m0 = blockIdx.x * 64, n0 = blockIdx.y * 64;
    const int tid = threadIdx.x, tx = tid & 15, ty = tid >> 4;

    __shared__ float2 As[32][64];
    __shared__ float  Ws[32][64];

    u64 acc[4][2];
    #pragma unroll
    for (int r = 0; r < 4; r++){ acc[r][0] = 0ull; acc[r][1] = 0ull; }

    for (int kk = 0; kk < Kdim; kk += 32){
        __syncthreads();
        {
            int row = tid >> 2;
            const float* ar = A + (size_t)(m0 + row) * Kdim + kk;
            const float* wr = W + (size_t)(n0 + row) * Kdim + kk;
            #pragma unroll
            for (int hh = 0; hh < 2; hh++){
                int kb = ((tid & 3) << 2) + (hh << 4);
                float4 va = *reinterpret_cast<const float4*>(ar + kb);
                As[kb + 0][row] = make_float2(va.x, va.x);
                As[kb + 1][row] = make_float2(va.y, va.y);
                As[kb + 2][row] = make_float2(va.z, va.z);
                As[kb + 3][row] = make_float2(va.w, va.w);
                float4 vw = *reinterpret_cast<const float4*>(wr + kb);
                Ws[kb + 0][row] = vw.x;
                Ws[kb + 1][row] = vw.y;
                Ws[kb + 2][row] = vw.z;
                Ws[kb + 3][row] = vw.w;
            }
        }
        __syncthreads();
        #pragma unroll 8
        for (int k = 0; k < 32; k++){
            u64 b0 = *reinterpret_cast<const u64*>(&Ws[k][tx << 1]);
            u64 b1 = *reinterpret_cast<const u64*>(&Ws[k][(tx << 1) + 32]);
            #pragma unroll
            for (int r = 0; r < 4; r++){
                u64 a = *reinterpret_cast<const u64*>(&As[k][(ty << 2) + r]);
                acc[r][0] = ffma2(a, b0, acc[r][0]);
                acc[r][1] = ffma2(a, b1, acc[r][1]);
            }
        }
    }

    #pragma unroll
    for (int r = 0; r < 4; r++){
        int row = m0 + (ty << 2) + r;
        #pragma unroll
        for (int p = 0; p < 2; p++){
            int j = (tx << 1) + (p << 5);
            float c0, c1;
            unpack2(acc[r][p], c0, c1);
            c0 = fmaxf(c0 + bias[n0 + j],     0.0f);
            c1 = fmaxf(c1 + bias[n0 + j + 1], 0.0f);
            *reinterpret_cast<float2*>(&C[(size_t)row * Ndim + n0 + j]) = make_float2(c0, c1);
        }
    }
}

// ---------------- soft clustering (proven) ----------------
__global__ void __launch_bounds__(256) qkernel(
    const float* __restrict__ z, const float* __restrict__ cent, float* __restrict__ q)
{
    int warp = threadIdx.x >> 5, lane = threadIdx.x & 31;
    int b = blockIdx.x * 8 + warp;
    float zr[8];
    #pragma unroll
    for (int i = 0; i < 8; i++) zr[i] = z[(size_t)b * Hsz + lane + 32 * i];
    float s = 0.0f;
    for (int k = 0; k < Ksz; k++){
        float d = 0.0f;
        #pragma unroll
        for (int i = 0; i < 8; i++){
            float t = zr[i] - cent[k * Hsz + lane + 32 * i];
            d = fmaf(t, t, d);
        }
        #pragma unroll
        for (int off = 16; off; off >>= 1) d += __shfl_xor_sync(0xffffffffu, d, off);
        if (lane == k) s = 1.0f / (1.0f + d);
    }
    float tot = s;
    #pragma unroll
    for (int off = 16; off; off >>= 1) tot += __shfl_xor_sync(0xffffffffu, tot, off);
    if (lane < Ksz) q[(size_t)b * Ksz + lane] = s / tot;
}

// ---------------- logits + combine (proven) ----------------
__global__ void __launch_bounds__(256) combine_kernel(
    const float* __restrict__ h2, const float* __restrict__ q,
    const float* __restrict__ eW3, const float* __restrict__ eb3,
    float* __restrict__ out)
{
    int warp = threadIdx.x >> 5, lane = threadIdx.x & 31;
    int b = blockIdx.x * 8 + warp;
    float acc[Ksz][2];
    #pragma unroll
    for (int k = 0; k < Ksz; k++){ acc[k][0] = 0.0f; acc[k][1] = 0.0f; }
    for (int f = lane; f < E2sz; f += 32){
        #pragma unroll
        for (int k = 0; k < Ksz; k++){
            float hv = h2[((size_t)k * Bsz + b) * E2sz + f];
            acc[k][0] = fmaf(hv, eW3[(size_t)(k * 2 + 0) * E2sz + f], acc[k][0]);
            acc[k][1] = fmaf(hv, eW3[(size_t)(k * 2 + 1) * E2sz + f], acc[k][1]);
        }
    }
    #pragma unroll
    for (int k = 0; k < Ksz; k++)
        #pragma unroll
        for (int c = 0; c < 2; c++)
            #pragma unroll
            for (int off = 16; off; off >>= 1)
                acc[k][c] += __shfl_xor_sync(0xffffffffu, acc[k][c], off);
    if (lane == 0){
        float p0 = 0.0f, p1 = 0.0f;
        #pragma unroll
        for (int k = 0; k < Ksz; k++){
            float qq = q[(size_t)b * Ksz + k];
            p0 = fmaf(qq, acc[k][0] + eb3[k * 2 + 0], p0);
            p1 = fmaf(qq, acc[k][1] + eb3[k * 2 + 1], p1);
        }
        out[b * 2 + 0] = p0;
        out[b * 2 + 1] = p1;
    }
}

// ---------------------------------------------------------------------------
#define STEP_SMEM_FUSE   ((2 * 256 * 96 + 64 * 64) * 4)   /* 212992 */
#define STEP_SMEM_PLAIN  ((256 * 96 + 64 * 64) * 4)       /* 114688 */
#define GEMM_SMEM        ((64 * 128 + 64 * 64) * 4)       /* 49152  */

extern "C" void kernel_launch(void* const* d_in, const int* in_sizes, int n_in,
                              void* d_out, int out_size)
{
    const float* x    = (const float*)d_in[0];
    const float* Wih0 = (const float*)d_in[1];
    const float* Whh0 = (const float*)d_in[2];
    const float* bih0 = (const float*)d_in[3];
    const float* bhh0 = (const float*)d_in[4];
    const float* Wih1 = (const float*)d_in[5];
    const float* Whh1 = (const float*)d_in[6];
    const float* bih1 = (const float*)d_in[7];
    const float* bhh1 = (const float*)d_in[8];
    const float* cent = (const float*)d_in[9];
    const float* eW1  = (const float*)d_in[10];
    const float* eb1  = (const float*)d_in[11];
    const float* eW2  = (const float*)d_in[12];
    const float* eb2  = (const float*)d_in[13];
    const float* eW3  = (const float*)d_in[14];
    const float* eb3  = (const float*)d_in[15];
    float* out = (float*)d_out;

    float *xT, *WihT0, *WhhT0, *WihT1, *WhhT1, *gi0, *gi1, *hl0T, *h1T, *z, *qb, *e1, *e2;
    cudaGetSymbolAddress((void**)&xT,    g_xT);
    cudaGetSymbolAddress((void**)&WihT0, g_WihT0);
    cudaGetSymbolAddress((void**)&WhhT0, g_WhhT0);
    cudaGetSymbolAddress((void**)&WihT1, g_WihT1);
    cudaGetSymbolAddress((void**)&WhhT1, g_WhhT1);
    cudaGetSymbolAddress((void**)&gi0,   g_gi0);
    cudaGetSymbolAddress((void**)&gi1,   g_gi1);
    cudaGetSymbolAddress((void**)&hl0T,  g_hl0T);
    cudaGetSymbolAddress((void**)&h1T,   g_h1T);
    cudaGetSymbolAddress((void**)&z,     g_z);
    cudaGetSymbolAddress((void**)&qb,    g_q);
    cudaGetSymbolAddress((void**)&e1,    g_e1);
    cudaGetSymbolAddress((void**)&e2,    g_e2);

    cudaFuncSetAttribute(gru_step<false, true>,
                         cudaFuncAttributeMaxDynamicSharedMemorySize, STEP_SMEM_FUSE);
    cudaFuncSetAttribute(gru_step<false, false>,
                         cudaFuncAttributeMaxDynamicSharedMemorySize, STEP_SMEM_PLAIN);
    cudaFuncSetAttribute(gemm_tn,
                         cudaFuncAttributeMaxDynamicSharedMemorySize, GEMM_SMEM);

    const size_t PG = (size_t)Bsz * G3;    // per-t gi plane
    const size_t PH = (size_t)Hsz * Bsz;   // per-buffer hT plane
    dim3 sg(16, 8);

    // ---- one-time layout transforms ----
    transpose_s<<<dim3(4, 32, 128), 256>>>(x, (size_t)Tsz * Isz, (size_t)Isz,
                                           xT, (size_t)Bsz, (size_t)Isz * Bsz);
    transpose_s<<<dim3(4, 24, 1), 256>>>(Wih0, Isz, 0, WihT0, G3, 0);
    transpose_s<<<dim3(8, 24, 1), 256>>>(Whh0, Hsz, 0, WhhT0, G3, 0);
    transpose_s<<<dim3(8, 24, 1), 256>>>(Wih1, Hsz, 0, WihT1, G3, 0);
    transpose_s<<<dim3(8, 24, 1), 256>>>(Whh1, Hsz, 0, WhhT1, G3, 0);

    // ---- gi0 = x @ Wih0^T for all (t,b) : M = 131072, K = 128, N = 768 ----
    gemm_tn<<<dim3(1024, 12), 256, GEMM_SMEM>>>(
        xT, (size_t)Bsz, (size_t)Isz * Bsz, Bsz, WihT0, G3, Isz, gi0);

    // ---- layer 0 chain (fused: step t also emits gi1[t-1]) ----
    gru_step<true, false><<<sg, 256, 0>>>(
        hl0T, WhhT0, WihT1, gi0, bih0, bhh0, hl0T, gi1);
    for (int t = 1; t < Tsz; t++){
        gru_step<false, true><<<sg, 256, STEP_SMEM_FUSE>>>(
            hl0T + ((t - 1) & 1) * PH, WhhT0, WihT1, gi0 + (size_t)t * PG,
            bih0, bhh0, hl0T + (t & 1) * PH, gi1 + (size_t)(t - 1) * PG);
    }
    // gi1[127] from hl0T[127 & 1 = 1]
    gemm_tn<<<dim3(8, 12), 256, GEMM_SMEM>>>(
        hl0T + PH, (size_t)Bsz, 0, Bsz, WihT1, G3, Hsz, gi1 + (size_t)127 * PG);

    // ---- layer 1 chain (gh only) ----
    gru_step<true, false><<<sg, 256, 0>>>(
        h1T, WhhT1, WihT1, gi1, bih1, bhh1, h1T, gi1);
    for (int t = 1; t < Tsz; t++){
        gru_step<false, false><<<sg, 256, STEP_SMEM_PLAIN>>>(
            h1T + ((t - 1) & 1) * PH, WhhT1, WihT1, gi1 + (size_t)t * PG,
            bih1, bhh1, h1T + (t & 1) * PH, gi1);
    }

    // ---- z = h1T[1]^T  ([256][1024] -> [1024][256]) ----
    transpose_s<<<dim3(32, 8, 1), 256>>>(h1T + PH, Bsz, 0, z, Hsz, 0);

    // ---- clustering + experts + combine ----
    qkernel<<<128, 256>>>(z, cent, qb);
    gemm_relu_kernel<<<dim3(16, 8, 8), 256>>>(
        z, (size_t)0, eW1, (size_t)E1sz * Hsz, eb1, (size_t)E1sz,
        e1, (size_t)Bsz * E1sz, Hsz, E1sz);
    gemm_relu_kernel<<<dim3(16, 4, 8), 256>>>(
        e1, (size_t)Bsz * E1sz, eW2, (size_t)E2sz * E1sz, eb2, (size_t)E2sz,
        e2, (size_t)Bsz * E2sz, E1sz, E2sz);
    combine_kernel<<<128, 256>>>(e2, qb, eW3, eb3, out);

    (void)in_sizes; (void)n_in; (void)out_size;
}

// round 7
// speedup vs baseline: 1.3745x; 1.0942x over previous
#include <cuda_runtime.h>
#include <cstddef>

#define Bsz  1024
#define Tsz  128
#define Isz  128
#define Hsz  256
#define G3   768
#define Ksz  8
#define E1sz 512
#define E2sz 256

typedef unsigned long long u64;
struct alignas(16) U64x2 { u64 lo, hi; };

__device__ __forceinline__ u64 ffma2(u64 a, u64 b, u64 c){
    u64 d; asm("fma.rn.f32x2 %0, %1, %2, %3;" : "=l"(d) : "l"(a), "l"(b), "l"(c)); return d;
}
__device__ __forceinline__ void unpack2(u64 v, float& lo, float& hi){
    asm("mov.b64 {%0, %1}, %2;" : "=f"(lo), "=f"(hi) : "l"(v));
}
__device__ __forceinline__ u64 pack2(float x, float y){
    u64 v; asm("mov.b64 %0, {%1, %2};" : "=l"(v) : "f"(x), "f"(y)); return v;
}
__device__ __forceinline__ float sigmoidf_(float x){
    return __fdividef(1.0f, 1.0f + __expf(-x));
}
__device__ __forceinline__ float tanhf_(float x){
    return 1.0f - __fdividef(2.0f, __expf(2.0f * x) + 1.0f);
}

// ---------------- scratch ----------------
__device__ float g_xT[(size_t)Tsz * Isz * Bsz];      // [t][k][b]
__device__ float g_WihT0[(size_t)Isz * G3];
__device__ float g_WhhT0[(size_t)Hsz * G3];
__device__ float g_WihT1[(size_t)Hsz * G3];
__device__ float g_WhhT1[(size_t)Hsz * G3];
__device__ float g_gi0[(size_t)Tsz * Bsz * G3];
__device__ float g_gi1[(size_t)Tsz * Bsz * G3];
__device__ float g_hl0T[2][(size_t)Hsz * Bsz];       // ping-pong [h][b]
__device__ float g_h1T[2][(size_t)Hsz * Bsz];
__device__ float g_z[(size_t)Bsz * Hsz];
__device__ float g_q[Bsz * Ksz];
__device__ float g_e1[(size_t)Ksz * Bsz * E1sz];
__device__ float g_e2[(size_t)Ksz * Bsz * E2sz];

// barrier state (zero-init; self-maintaining across launches: counters return to
// 0 after every completed barrier, generation targets are entry-relative)
__device__ unsigned g_cnt0, g_gen0, g_cnt1, g_gen1;

// ---------------- software grid barrier (all CTAs resident by construction) ---
__device__ __forceinline__ void grid_bar(unsigned* cnt, volatile unsigned* gen,
                                         unsigned target, unsigned nCTAm1){
    __syncthreads();
    if (threadIdx.x == 0){
        __threadfence();
        if (atomicAdd(cnt, 1u) == nCTAm1){
            atomicExch(cnt, 0u);
            __threadfence();
            *gen = target;
        } else {
            while (*gen < target) { }
        }
        __threadfence();
    }
    __syncthreads();
}

// ---------------- strided 32x32 transpose: out[c][r] = in[r][c] ----------------
__global__ void __launch_bounds__(256) transpose_s(
    const float* __restrict__ in, size_t inRS, size_t inZ,
    float* __restrict__ out, size_t outRS, size_t outZ)
{
    in  += (size_t)blockIdx.z * inZ;
    out += (size_t)blockIdx.z * outZ;
    __shared__ float t[32][33];
    const int tx = threadIdx.x & 31, ty = threadIdx.x >> 5;
    const int r0 = blockIdx.y * 32, c0 = blockIdx.x * 32;
    #pragma unroll
    for (int i = 0; i < 4; i++)
        t[ty + 8 * i][tx] = in[(size_t)(r0 + ty + 8 * i) * inRS + c0 + tx];
    __syncthreads();
    #pragma unroll
    for (int i = 0; i < 4; i++)
        out[(size_t)(c0 + ty + 8 * i) * outRS + r0 + tx] = t[tx][ty + 8 * i];
}

// ---------------------------------------------------------------------------
// TN GEMM (for gi0): C[m][n] = sum_k AT(k,m) * WT[k][n]
// ---------------------------------------------------------------------------
__global__ void __launch_bounds__(256) gemm_tn(
    const float* __restrict__ AT, size_t aRowStride, size_t aBlkStride, int mBlk,
    const float* __restrict__ WT, int N, int K, float* __restrict__ C)
{
    extern __shared__ float sm[];
    float* As = sm;              // [64][128]
    float* Bs = sm + 64 * 128;   // [64][64]
    const int tid = threadIdx.x, w = tid >> 5, lane = tid & 31;
    const int m0 = blockIdx.x * 128, n0 = blockIdx.y * 64;
    const int jl = w * 8;
    const float* Abase = AT + (size_t)(m0 / mBlk) * aBlkStride + (m0 % mBlk);

    u64 acc[4][4];
    #pragma unroll
    for (int r = 0; r < 4; r++)
        #pragma unroll
        for (int q = 0; q < 4; q++) acc[r][q] = 0ull;

    for (int kk = 0; kk < K; kk += 64){
        __syncthreads();
        for (int i = tid; i < 64 * 32; i += 256){
            int k = i >> 5, q = i & 31;
            *reinterpret_cast<float4*>(As + k * 128 + q * 4) =
                *reinterpret_cast<const float4*>(Abase + (size_t)(kk + k) * aRowStride + q * 4);
        }
        for (int i = tid; i < 64 * 16; i += 256){
            int k = i >> 4, q = i & 15;
            *reinterpret_cast<float4*>(Bs + k * 64 + q * 4) =
                *reinterpret_cast<const float4*>(WT + (size_t)(kk + k) * N + n0 + q * 4);
        }
        __syncthreads();
        #pragma unroll 8
        for (int k = 0; k < 64; k++){
            U64x2 ap = *reinterpret_cast<const U64x2*>(As + k * 128 + 4 * lane);
            float f0, f1, f2, f3;
            unpack2(ap.lo, f0, f1); unpack2(ap.hi, f2, f3);
            u64 ad[4] = { pack2(f0, f0), pack2(f1, f1), pack2(f2, f2), pack2(f3, f3) };
            U64x2 b01 = *reinterpret_cast<const U64x2*>(Bs + k * 64 + jl);
            U64x2 b23 = *reinterpret_cast<const U64x2*>(Bs + k * 64 + jl + 4);
            u64 bq[4] = { b01.lo, b01.hi, b23.lo, b23.hi };
            #pragma unroll
            for (int r = 0; r < 4; r++)
                #pragma unroll
                for (int q = 0; q < 4; q++)
                    acc[r][q] = ffma2(ad[r], bq[q], acc[r][q]);
        }
    }

    #pragma unroll
    for (int r = 0; r < 4; r++){
        int row = m0 + 4 * lane + r;
        float o[8];
        #pragma unroll
        for (int q = 0; q < 4; q++) unpack2(acc[r][q], o[2 * q], o[2 * q + 1]);
        *reinterpret_cast<float4*>(C + (size_t)row * N + n0 + jl) =
            make_float4(o[0], o[1], o[2], o[3]);
        *reinterpret_cast<float4*>(C + (size_t)row * N + n0 + jl + 4) =
            make_float4(o[4], o[5], o[6], o[7]);
    }
}

// ---------------------------------------------------------------------------
// Persistent GRU layer: all 128 steps in ONE kernel, grid (16,8)=128 CTAs,
// software grid barrier between steps. Weight slices live in smem for the
// whole layer. FUSE: also emits gi1[t-1] = h[t-1] @ Wih1^T per step, and the
// final gi1[127] in a tail phase.
// All h arrays transposed [256][1024]; h reads via __ldcg (cross-CTA in-kernel).
// ---------------------------------------------------------------------------
template<bool FUSE>
__global__ void __launch_bounds__(256) gru_persist(
    const float* __restrict__ WhhT, const float* __restrict__ WihTn,
    const float* __restrict__ giAll,
    const float* __restrict__ bih, const float* __restrict__ bhh,
    float* __restrict__ hbuf,        // [2][256][1024]
    float* __restrict__ gi1out,      // [T][B][768] (FUSE only)
    unsigned* cnt, unsigned* genp)
{
    extern __shared__ float sm[];
    float* Bhh = sm;                                 // [256][96]
    float* Bih = sm + 256 * 96;                      // [256][96] (FUSE)
    float* As  = sm + (FUSE ? 2 : 1) * 256 * 96;     // [64][64]
    const int tid = threadIdx.x, w = tid >> 5, lane = tid & 31;
    const int m0 = blockIdx.x * 64, n0 = blockIdx.y * 32;
    const int jl = w * 4, ml = lane * 2;
    const size_t PH = (size_t)Hsz * Bsz, PG = (size_t)Bsz * G3;

    // ---- one-time weight slice load ----
    for (int i = tid; i < 256 * 24; i += 256){
        int k = i / 24, c = i - k * 24, g = c >> 3, q = c & 7;
        *reinterpret_cast<float4*>(Bhh + k * 96 + g * 32 + q * 4) =
            *reinterpret_cast<const float4*>(WhhT + (size_t)k * G3 + g * Hsz + n0 + q * 4);
        if constexpr (FUSE)
            *reinterpret_cast<float4*>(Bih + k * 96 + g * 32 + q * 4) =
                *reinterpret_cast<const float4*>(WihTn + (size_t)k * G3 + g * Hsz + n0 + q * 4);
    }

    float bi[3][4], bh_[3][4];
    #pragma unroll
    for (int g = 0; g < 3; g++){
        *reinterpret_cast<float4*>(bi[g]) =
            *reinterpret_cast<const float4*>(bih + g * Hsz + n0 + jl);
        *reinterpret_cast<float4*>(bh_[g]) =
            *reinterpret_cast<const float4*>(bhh + g * Hsz + n0 + jl);
    }

    volatile unsigned* gen = genp;
    const unsigned gbase = *gen;     // entry-relative generation base
    __syncthreads();

    for (int t = 0; t < Tsz; t++){
        const float* HprevT = hbuf + (size_t)((t - 1) & 1) * PH;   // unused at t=0
        float*       HnewT  = hbuf + (size_t)(t & 1) * PH;
        const float* gi     = giAll + (size_t)t * PG;

        u64 aH[3][2][2], aI[3][2][2];
        #pragma unroll
        for (int g = 0; g < 3; g++)
            #pragma unroll
            for (int cp = 0; cp < 2; cp++)
                #pragma unroll
                for (int r = 0; r < 2; r++){ aH[g][cp][r] = 0ull; aI[g][cp][r] = 0ull; }

        if (t > 0){
            for (int kk = 0; kk < Hsz; kk += 64){
                __syncthreads();
                for (int i = tid; i < 64 * 16; i += 256){
                    int k = i >> 4, q = i & 15;
                    *reinterpret_cast<float4*>(As + k * 64 + q * 4) =
                        __ldcg(reinterpret_cast<const float4*>(
                            HprevT + (size_t)(kk + k) * Bsz + m0 + q * 4));
                }
                __syncthreads();
                #pragma unroll 8
                for (int k = 0; k < 64; k++){
                    u64 a01 = *reinterpret_cast<const u64*>(As + k * 64 + ml);
                    float a0f, a1f; unpack2(a01, a0f, a1f);
                    u64 a0 = pack2(a0f, a0f), a1 = pack2(a1f, a1f);
                    const float* bh = Bhh + (size_t)(kk + k) * 96 + jl;
                    #pragma unroll
                    for (int g = 0; g < 3; g++){
                        U64x2 bb = *reinterpret_cast<const U64x2*>(bh + g * 32);
                        aH[g][0][0] = ffma2(a0, bb.lo, aH[g][0][0]);
                        aH[g][0][1] = ffma2(a1, bb.lo, aH[g][0][1]);
                        aH[g][1][0] = ffma2(a0, bb.hi, aH[g][1][0]);
                        aH[g][1][1] = ffma2(a1, bb.hi, aH[g][1][1]);
                    }
                    if constexpr (FUSE){
                        const float* bi2 = Bih + (size_t)(kk + k) * 96 + jl;
                        #pragma unroll
                        for (int g = 0; g < 3; g++){
                            U64x2 bb = *reinterpret_cast<const U64x2*>(bi2 + g * 32);
                            aI[g][0][0] = ffma2(a0, bb.lo, aI[g][0][0]);
                            aI[g][0][1] = ffma2(a1, bb.lo, aI[g][0][1]);
                            aI[g][1][0] = ffma2(a0, bb.hi, aI[g][1][0]);
                            aI[g][1][1] = ffma2(a1, bb.hi, aI[g][1][1]);
                        }
                    }
                }
            }
        }

        // ---- epilogue ----
        float gh[3][2][4];
        if (t > 0){
            #pragma unroll
            for (int g = 0; g < 3; g++)
                #pragma unroll
                for (int cp = 0; cp < 2; cp++)
                    #pragma unroll
                    for (int r = 0; r < 2; r++)
                        unpack2(aH[g][cp][r], gh[g][r][2 * cp], gh[g][r][2 * cp + 1]);
        } else {
            #pragma unroll
            for (int g = 0; g < 3; g++)
                #pragma unroll
                for (int r = 0; r < 2; r++)
                    #pragma unroll
                    for (int c = 0; c < 4; c++) gh[g][r][c] = 0.0f;
        }

        float hp[2][4];
        #pragma unroll
        for (int r = 0; r < 2; r++)
            #pragma unroll
            for (int c = 0; c < 4; c++) hp[r][c] = 0.0f;
        if (t > 0){
            #pragma unroll
            for (int c = 0; c < 4; c++){
                float2 v = __ldcg(reinterpret_cast<const float2*>(
                    HprevT + (size_t)(n0 + jl + c) * Bsz + m0 + ml));
                hp[0][c] = v.x; hp[1][c] = v.y;
            }
        }

        float hn[2][4];
        #pragma unroll
        for (int r = 0; r < 2; r++){
            const float* gr = gi + (size_t)(m0 + ml + r) * G3;
            float gv[3][4];
            #pragma unroll
            for (int g = 0; g < 3; g++)
                *reinterpret_cast<float4*>(gv[g]) =
                    *reinterpret_cast<const float4*>(gr + g * Hsz + n0 + jl);
            #pragma unroll
            for (int c = 0; c < 4; c++){
                float rg = sigmoidf_(gv[0][c] + bi[0][c] + gh[0][r][c] + bh_[0][c]);
                float zg = sigmoidf_(gv[1][c] + bi[1][c] + gh[1][r][c] + bh_[1][c]);
                float ng = tanhf_(gv[2][c] + bi[2][c] + rg * (gh[2][r][c] + bh_[2][c]));
                hn[r][c] = (1.0f - zg) * ng + zg * hp[r][c];
            }
        }
        #pragma unroll
        for (int c = 0; c < 4; c++)
            *reinterpret_cast<float2*>(HnewT + (size_t)(n0 + jl + c) * Bsz + m0 + ml) =
                make_float2(hn[0][c], hn[1][c]);

        if constexpr (FUSE){
            if (t > 0){
                #pragma unroll
                for (int r = 0; r < 2; r++){
                    float* go = gi1out + (size_t)(t - 1) * PG + (size_t)(m0 + ml + r) * G3;
                    #pragma unroll
                    for (int g = 0; g < 3; g++){
                        float o0, o1, o2, o3;
                        unpack2(aI[g][0][r], o0, o1);
                        unpack2(aI[g][1][r], o2, o3);
                        *reinterpret_cast<float4*>(go + g * Hsz + n0 + jl) =
                            make_float4(o0, o1, o2, o3);
                    }
                }
            }
        }

        grid_bar(cnt, gen, gbase + (unsigned)t + 1u, 127u);
    }

    // ---- FUSE tail: gi1[127] = h[127] @ Wih1^T ----
    if constexpr (FUSE){
        const float* HpT = hbuf + PH;   // h[127] lives in buffer (127&1)=1
        u64 aI[3][2][2];
        #pragma unroll
        for (int g = 0; g < 3; g++)
            #pragma unroll
            for (int cp = 0; cp < 2; cp++){ aI[g][cp][0] = 0ull; aI[g][cp][1] = 0ull; }
        for (int kk = 0; kk < Hsz; kk += 64){
            __syncthreads();
            for (int i = tid; i < 64 * 16; i += 256){
                int k = i >> 4, q = i & 15;
                *reinterpret_cast<float4*>(As + k * 64 + q * 4) =
                    __ldcg(reinterpret_cast<const float4*>(
                        HpT + (size_t)(kk + k) * Bsz + m0 + q * 4));
            }
            __syncthreads();
            #pragma unroll 8
            for (int k = 0; k < 64; k++){
                u64 a01 = *reinterpret_cast<const u64*>(As + k * 64 + ml);
                float a0f, a1f; unpack2(a01, a0f, a1f);
                u64 a0 = pack2(a0f, a0f), a1 = pack2(a1f, a1f);
                const float* bi2 = Bih + (size_t)(kk + k) * 96 + jl;
                #pragma unroll
                for (int g = 0; g < 3; g++){
                    U64x2 bb = *reinterpret_cast<const U64x2*>(bi2 + g * 32);
                    aI[g][0][0] = ffma2(a0, bb.lo, aI[g][0][0]);
                    aI[g][0][1] = ffma2(a1, bb.lo, aI[g][0][1]);
                    aI[g][1][0] = ffma2(a0, bb.hi, aI[g][1][0]);
                    aI[g][1][1] = ffma2(a1, bb.hi, aI[g][1][1]);
                }
            }
        }
        #pragma unroll
        for (int r = 0; r < 2; r++){
            float* go = gi1out + (size_t)127 * PG + (size_t)(m0 + ml + r) * G3;
            #pragma unroll
            for (int g = 0; g < 3; g++){
                float o0, o1, o2, o3;
                unpack2(aI[g][0][r], o0, o1);
                unpack2(aI[g][1][r], o2, o3);
                *reinterpret_cast<float4*>(go + g * Hsz + n0 + jl) =
                    make_float4(o0, o1, o2, o3);
            }
        }
    }
}

// ---------------------------------------------------------------------------
// Per-expert NT GEMM + relu (proven)
// ---------------------------------------------------------------------------
__global__ void __launch_bounds__(256) gemm_relu_kernel(
    const float* __restrict__ Abase, size_t aStride,
    const float* __restrict__ Wbase, size_t wStride,
    const float* __restrict__ biasBase, size_t bStride,
    float* __restrict__ Cbase, size_t cStride,
    int Kdim, int Ndim)
{
    const int e = blockIdx.z;
    const float* A    = Abase    + (size_t)e * aStride;
    const float* W    = Wbase    + (size_t)e * wStride;
    const float* bias = biasBase + (size_t)e * bStride;
    float*       C    = Cbase    + (size_t)e * cStride;

    const int m0 = blockIdx.x * 64, n0 = blockIdx.y * 64;
    const int tid = threadIdx.x, tx = tid & 15, ty = tid >> 4;

    __shared__ float2 As[32][64];
    __shared__ float  Ws[32][64];

    u64 acc[4][2];
    #pragma unroll
    for (int r = 0; r < 4; r++){ acc[r][0] = 0ull; acc[r][1] = 0ull; }

    for (int kk = 0; kk < Kdim; kk += 32){
        __syncthreads();
        {
            int row = tid >> 2;
            const float* ar = A + (size_t)(m0 + row) * Kdim + kk;
            const float* wr = W + (size_t)(n0 + row) * Kdim + kk;
            #pragma unroll
            for (int hh = 0; hh < 2; hh++){
                int kb = ((tid & 3) << 2) + (hh << 4);
                float4 va = *reinterpret_cast<const float4*>(ar + kb);
                As[kb + 0][row] = make_float2(va.x, va.x);
                As[kb + 1][row] = make_float2(va.y, va.y);
                As[kb + 2][row] = make_float2(va.z, va.z);
                As[kb + 3][row] = make_float2(va.w, va.w);
                float4 vw = *reinterpret_cast<const float4*>(wr + kb);
                Ws[kb + 0][row] = vw.x;
                Ws[kb + 1][row] = vw.y;
                Ws[kb + 2][row] = vw.z;
                Ws[kb + 3][row] = vw.w;
            }
        }
        __syncthreads();
        #pragma unroll 8
        for (int k = 0; k < 32; k++){
            u64 b0 = *reinterpret_cast<const u64*>(&Ws[k][tx << 1]);
            u64 b1 = *reinterpret_cast<const u64*>(&Ws[k][(tx << 1) + 32]);
            #pragma unroll
            for (int r = 0; r < 4; r++){
                u64 a = *reinterpret_cast<const u64*>(&As[k][(ty << 2) + r]);
                acc[r][0] = ffma2(a, b0, acc[r][0]);
                acc[r][1] = ffma2(a, b1, acc[r][1]);
            }
        }
    }

    #pragma unroll
    for (int r = 0; r < 4; r++){
        int row = m0 + (ty << 2) + r;
        #pragma unroll
        for (int p = 0; p < 2; p++){
            int j = (tx << 1) + (p << 5);
            float c0, c1;
            unpack2(acc[r][p], c0, c1);
            c0 = fmaxf(c0 + bias[n0 + j],     0.0f);
            c1 = fmaxf(c1 + bias[n0 + j + 1], 0.0f);
            *reinterpret_cast<float2*>(&C[(size_t)row * Ndim + n0 + j]) = make_float2(c0, c1);
        }
    }
}

// ---------------- soft clustering (proven) ----------------
__global__ void __launch_bounds__(256) qkernel(
    const float* __restrict__ z, const float* __restrict__ cent, float* __restrict__ q)
{
    int warp = threadIdx.x >> 5, lane = threadIdx.x & 31;
    int b = blockIdx.x * 8 + warp;
    float zr[8];
    #pragma unroll
    for (int i = 0; i < 8; i++) zr[i] = z[(size_t)b * Hsz + lane + 32 * i];
    float s = 0.0f;
    for (int k = 0; k < Ksz; k++){
        float d = 0.0f;
        #pragma unroll
        for (int i = 0; i < 8; i++){
            float t = zr[i] - cent[k * Hsz + lane + 32 * i];
            d = fmaf(t, t, d);
        }
        #pragma unroll
        for (int off = 16; off; off >>= 1) d += __shfl_xor_sync(0xffffffffu, d, off);
        if (lane == k) s = 1.0f / (1.0f + d);
    }
    float tot = s;
    #pragma unroll
    for (int off = 16; off; off >>= 1) tot += __shfl_xor_sync(0xffffffffu, tot, off);
    if (lane < Ksz) q[(size_t)b * Ksz + lane] = s / tot;
}

// ---------------- logits + combine (proven) ----------------
__global__ void __launch_bounds__(256) combine_kernel(
    const float* __restrict__ h2, const float* __restrict__ q,
    const float* __restrict__ eW3, const float* __restrict__ eb3,
    float* __restrict__ out)
{
    int warp = threadIdx.x >> 5, lane = threadIdx.x & 31;
    int b = blockIdx.x * 8 + warp;
    float acc[Ksz][2];
    #pragma unroll
    for (int k = 0; k < Ksz; k++){ acc[k][0] = 0.0f; acc[k][1] = 0.0f; }
    for (int f = lane; f < E2sz; f += 32){
        #pragma unroll
        for (int k = 0; k < Ksz; k++){
            float hv = h2[((size_t)k * Bsz + b) * E2sz + f];
            acc[k][0] = fmaf(hv, eW3[(size_t)(k * 2 + 0) * E2sz + f], acc[k][0]);
            acc[k][1] = fmaf(hv, eW3[(size_t)(k * 2 + 1) * E2sz + f], acc[k][1]);
        }
    }
    #pragma unroll
    for (int k = 0; k < Ksz; k++)
        #pragma unroll
        for (int c = 0; c < 2; c++)
            #pragma unroll
            for (int off = 16; off; off >>= 1)
                acc[k][c] += __shfl_xor_sync(0xffffffffu, acc[k][c], off);
    if (lane == 0){
        float p0 = 0.0f, p1 = 0.0f;
        #pragma unroll
        for (int k = 0; k < Ksz; k++){
            float qq = q[(size_t)b * Ksz + k];
            p0 = fmaf(qq, acc[k][0] + eb3[k * 2 + 0], p0);
            p1 = fmaf(qq, acc[k][1] + eb3[k * 2 + 1], p1);
        }
        out[b * 2 + 0] = p0;
        out[b * 2 + 1] = p1;
    }
}

// ---------------------------------------------------------------------------
#define PERSIST_SMEM_FUSE   ((2 * 256 * 96 + 64 * 64) * 4)   /* 212992 */
#define PERSIST_SMEM_PLAIN  ((256 * 96 + 64 * 64) * 4)       /* 114688 */
#define GEMM_SMEM           ((64 * 128 + 64 * 64) * 4)       /* 49152  */

extern "C" void kernel_launch(void* const* d_in, const int* in_sizes, int n_in,
                              void* d_out, int out_size)
{
    const float* x    = (const float*)d_in[0];
    const float* Wih0 = (const float*)d_in[1];
    const float* Whh0 = (const float*)d_in[2];
    const float* bih0 = (const float*)d_in[3];
    const float* bhh0 = (const float*)d_in[4];
    const float* Wih1 = (const float*)d_in[5];
    const float* Whh1 = (const float*)d_in[6];
    const float* bih1 = (const float*)d_in[7];
    const float* bhh1 = (const float*)d_in[8];
    const float* cent = (const float*)d_in[9];
    const float* eW1  = (const float*)d_in[10];
    const float* eb1  = (const float*)d_in[11];
    const float* eW2  = (const float*)d_in[12];
    const float* eb2  = (const float*)d_in[13];
    const float* eW3  = (const float*)d_in[14];
    const float* eb3  = (const float*)d_in[15];
    float* out = (float*)d_out;

    float *xT, *WihT0, *WhhT0, *WihT1, *WhhT1, *gi0, *gi1, *hl0T, *h1T, *z, *qb, *e1, *e2;
    unsigned *cnt0, *gen0, *cnt1, *gen1;
    cudaGetSymbolAddress((void**)&xT,    g_xT);
    cudaGetSymbolAddress((void**)&WihT0, g_WihT0);
    cudaGetSymbolAddress((void**)&WhhT0, g_WhhT0);
    cudaGetSymbolAddress((void**)&WihT1, g_WihT1);
    cudaGetSymbolAddress((void**)&WhhT1, g_WhhT1);
    cudaGetSymbolAddress((void**)&gi0,   g_gi0);
    cudaGetSymbolAddress((void**)&gi1,   g_gi1);
    cudaGetSymbolAddress((void**)&hl0T,  g_hl0T);
    cudaGetSymbolAddress((void**)&h1T,   g_h1T);
    cudaGetSymbolAddress((void**)&z,     g_z);
    cudaGetSymbolAddress((void**)&qb,    g_q);
    cudaGetSymbolAddress((void**)&e1,    g_e1);
    cudaGetSymbolAddress((void**)&e2,    g_e2);
    cudaGetSymbolAddress((void**)&cnt0,  g_cnt0);
    cudaGetSymbolAddress((void**)&gen0,  g_gen0);
    cudaGetSymbolAddress((void**)&cnt1,  g_cnt1);
    cudaGetSymbolAddress((void**)&gen1,  g_gen1);

    cudaFuncSetAttribute(gru_persist<true>,
                         cudaFuncAttributeMaxDynamicSharedMemorySize, PERSIST_SMEM_FUSE);
    cudaFuncSetAttribute(gru_persist<false>,
                         cudaFuncAttributeMaxDynamicSharedMemorySize, PERSIST_SMEM_PLAIN);
    cudaFuncSetAttribute(gemm_tn,
                         cudaFuncAttributeMaxDynamicSharedMemorySize, GEMM_SMEM);

    const size_t PH = (size_t)Hsz * Bsz;
    dim3 sg(16, 8);

    // ---- one-time layout transforms ----
    transpose_s<<<dim3(4, 32, 128), 256>>>(x, (size_t)Tsz * Isz, (size_t)Isz,
                                           xT, (size_t)Bsz, (size_t)Isz * Bsz);
    transpose_s<<<dim3(4, 24, 1), 256>>>(Wih0, Isz, 0, WihT0, G3, 0);
    transpose_s<<<dim3(8, 24, 1), 256>>>(Whh0, Hsz, 0, WhhT0, G3, 0);
    transpose_s<<<dim3(8, 24, 1), 256>>>(Wih1, Hsz, 0, WihT1, G3, 0);
    transpose_s<<<dim3(8, 24, 1), 256>>>(Whh1, Hsz, 0, WhhT1, G3, 0);

    // ---- gi0 = x @ Wih0^T : M=131072, K=128, N=768 ----
    gemm_tn<<<dim3(1024, 12), 256, GEMM_SMEM>>>(
        xT, (size_t)Bsz, (size_t)Isz * Bsz, Bsz, WihT0, G3, Isz, gi0);

    // ---- layer 0: persistent 128-step chain (emits gi1 as it goes) ----
    gru_persist<true><<<sg, 256, PERSIST_SMEM_FUSE>>>(
        WhhT0, WihT1, gi0, bih0, bhh0, hl0T, gi1, cnt0, gen0);

    // ---- layer 1: persistent 128-step chain ----
    gru_persist<false><<<sg, 256, PERSIST_SMEM_PLAIN>>>(
        WhhT1, nullptr, gi1, bih1, bhh1, h1T, nullptr, cnt1, gen1);

    // ---- z = h1T[1]^T  ([256][1024] -> [1024][256]) ----
    transpose_s<<<dim3(32, 8, 1), 256>>>(h1T + PH, Bsz, 0, z, Hsz, 0);

    // ---- clustering + experts + combine ----
    qkernel<<<128, 256>>>(z, cent, qb);
    gemm_relu_kernel<<<dim3(16, 8, 8), 256>>>(
        z, (size_t)0, eW1, (size_t)E1sz * Hsz, eb1, (size_t)E1sz,
        e1, (size_t)Bsz * E1sz, Hsz, E1sz);
    gemm_relu_kernel<<<dim3(16, 4, 8), 256>>>(
        e1, (size_t)Bsz * E1sz, eW2, (size_t)E2sz * E1sz, eb2, (size_t)E2sz,
        e2, (size_t)Bsz * E2sz, E1sz, E2sz);
    combine_kernel<<<128, 256>>>(e2, qb, eW3, eb3, out);

    (void)in_sizes; (void)n_in; (void)out_size;
}